// round 17
// baseline (speedup 1.0000x reference)
#include <cuda_runtime.h>
#include <cuda_fp16.h>
#include <cstdint>
#include <math.h>

#define BATCH 16384
#define TT 7
#define DD 1024
#define HH 512
#define EE 64
#define NF 4
#define G4H 2048              // 4*H
#define KCOMB 1540            // D + H + 4

// Output offsets (float32 concat in reference return order)
#define OFF_TOPP  ((size_t)0)
#define OFF_TOPI  ((size_t)131072)
#define OFF_LOSS  ((size_t)262144)
#define OFF_FLOW  ((size_t)262145)
#define OFF_USAGE ((size_t)327681)
#define OFF_ADJ   ((size_t)327745)

// ------------------------- scratch (static, no allocs) -------------------------
__device__ float d_XS[(size_t)BATCH * TT * G4H];
__device__ float d_Hst[(size_t)BATCH * HH];
__device__ float d_Hst2[(size_t)BATCH * HH];
__device__ float d_Cst[(size_t)BATCH * HH];
__device__ float d_FH[(size_t)BATCH * HH];
__device__ float d_FLOW[(size_t)BATCH * NF];
__device__ float d_COMB[(size_t)BATCH * KCOMB];
__device__ float d_G1[(size_t)BATCH * DD];
__device__ float d_ADJ[(size_t)BATCH * EE];
__device__ float d_WIH2[(size_t)G4H * DD];
__device__ float d_WHH2[(size_t)G4H * HH];
__device__ float d_BSUM2[G4H];

// ------------------------- helpers -------------------------
__device__ __forceinline__ uint32_t smem_u32(const void* p) {
    uint32_t a;
    asm("{ .reg .u64 t; cvta.to.shared.u64 t, %1; cvt.u32.u64 %0, t; }" : "=r"(a) : "l"(p));
    return a;
}
__device__ __forceinline__ void ldsm_x4(uint32_t* r, uint32_t addr) {
    asm volatile("ldmatrix.sync.aligned.m8n8.x4.shared.b16 {%0,%1,%2,%3}, [%4];"
        : "=r"(r[0]), "=r"(r[1]), "=r"(r[2]), "=r"(r[3]) : "r"(addr));
}
__device__ __forceinline__ void ldsm_x2(uint32_t* r, uint32_t addr) {
    asm volatile("ldmatrix.sync.aligned.m8n8.x2.shared.b16 {%0,%1}, [%2];"
        : "=r"(r[0]), "=r"(r[1]) : "r"(addr));
}
__device__ __forceinline__ void mma1688(float* c, const uint32_t* a,
                                        uint32_t b0, uint32_t b1) {
    asm volatile(
        "mma.sync.aligned.m16n8k8.row.col.f32.tf32.tf32.f32 "
        "{%0,%1,%2,%3}, {%4,%5,%6,%7}, {%8,%9}, {%0,%1,%2,%3};"
        : "+f"(c[0]), "+f"(c[1]), "+f"(c[2]), "+f"(c[3])
        : "r"(a[0]), "r"(a[1]), "r"(a[2]), "r"(a[3]), "r"(b0), "r"(b1));
}
__device__ __forceinline__ void mma16816(float* c, const uint32_t* a, const uint32_t* b) {
    asm volatile(
        "mma.sync.aligned.m16n8k16.row.col.f32.f16.f16.f32 "
        "{%0,%1,%2,%3}, {%4,%5,%6,%7}, {%8,%9}, {%0,%1,%2,%3};"
        : "+f"(c[0]), "+f"(c[1]), "+f"(c[2]), "+f"(c[3])
        : "r"(a[0]), "r"(a[1]), "r"(a[2]), "r"(a[3]), "r"(b[0]), "r"(b[1]));
}
__device__ __forceinline__ float tf32_rnd(float v) {
    float r; asm("cvt.rna.tf32.f32 %0, %1;" : "=f"(r) : "f"(v)); return r;
}
__device__ __forceinline__ void tsplit(float v, float& h, float& l) {
    h = tf32_rnd(v);
    l = tf32_rnd(v - h);
}
// pack two fp32 (tf32-valued) into fp16x2: first arg -> LOW half, second -> HIGH
__device__ __forceinline__ uint32_t pack2f(uint32_t lo_bits, uint32_t hi_bits) {
    uint32_t r;
    asm("cvt.rn.f16x2.f32 %0, %1, %2;"
        : "=r"(r) : "f"(__uint_as_float(hi_bits)), "f"(__uint_as_float(lo_bits)));
    return r;
}
__device__ __forceinline__ float sigmoidf(float x) { return 1.f / (1.f + expf(-x)); }

// permuted lo store: within each 8-col group, k'<4 -> col 2k', k'>=4 -> col 2(k'-4)+1
__device__ __forceinline__ void store_lo(char* arr, int row, int c4, float4 l) {
    __half* p = reinterpret_cast<__half*>(arr + row * 80);
    int col0 = (c4 & ~7) + ((c4 >> 2) & 1);
    p[col0 + 0] = __float2half_rn(l.x * 2048.f);
    p[col0 + 2] = __float2half_rn(l.y * 2048.f);
    p[col0 + 4] = __float2half_rn(l.z * 2048.f);
    p[col0 + 6] = __float2half_rn(l.w * 2048.f);
}

// Geometry: BM=64, BK=32 fp32-k, 256 threads (8 warps: 2 m-warps x 4 n-warps).
template<int BN>
struct GC {
    static constexpr int BM = 64, BK = 32, T = 256;
    static constexpr int NI = BN / 32;          // B n8-frags per warp
    static constexpr int WNW = BN / 4;          // warp n-extent
    static constexpr int P32 = 144;
    static constexpr int P16 = 80;
    static constexpr int A32SZ = BM * P32;
    static constexpr int B32SZ = BN * P32;
    static constexpr int A16SZ = BM * P16;
    static constexpr int B16SZ = BN * P16;
    static constexpr int OFF_B32  = A32SZ;
    static constexpr int OFF_A16L = OFF_B32 + B32SZ;
    static constexpr int OFF_B16L = OFF_A16L + A16SZ;
    static constexpr int STAGE = OFF_B16L + B16SZ;
    static constexpr int AV = BM * BK / 4 / T;  // 2
    static constexpr int BV = BN * BK / 4 / T;  // 4 or 2
};

#define GEMM_BODY(G, A_, lda_, W_, ldw_, K_)                                             \
    const int tid = threadIdx.x;                                                         \
    const int lane = tid & 31;                                                           \
    const int wid = tid >> 5;                                                            \
    const int wm = (wid & 1) * 32;                                                       \
    const int wn = (wid >> 1) * G::WNW;                                                  \
    const long m0 = (long)blockIdx.y * G::BM;                                            \
    const int  n0 = blockIdx.x * BN;                                                     \
    float Chh[2][G::NI][4], Ccr[2][G::NI][4];                                            \
    _Pragma("unroll")                                                                    \
    for (int i = 0; i < 2; i++)                                                          \
        _Pragma("unroll")                                                                \
        for (int j = 0; j < G::NI; j++)                                                  \
            _Pragma("unroll")                                                            \
            for (int q = 0; q < 4; q++) { Chh[i][j][q] = 0.f; Ccr[i][j][q] = 0.f; }      \
    float4 ra[G::AV], rb[G::BV];                                                         \
    auto load_chunk = [&](int ch) {                                                      \
        const int k0 = ch * G::BK;                                                       \
        _Pragma("unroll")                                                                \
        for (int q = 0; q < G::AV; q++) {                                                \
            int idx = tid + q * G::T;                                                    \
            int row = idx >> 3, c4 = (idx & 7) * 4;                                      \
            ra[q] = (k0 + c4 < K_)                                                       \
                ? *reinterpret_cast<const float4*>(A_ + (m0 + row) * (long)lda_ + k0 + c4)\
                : make_float4(0.f, 0.f, 0.f, 0.f);                                       \
        }                                                                                \
        _Pragma("unroll")                                                                \
        for (int q = 0; q < G::BV; q++) {                                                \
            int idx = tid + q * G::T;                                                    \
            int row = idx >> 3, c4 = (idx & 7) * 4;                                      \
            rb[q] = (k0 + c4 < K_)                                                       \
                ? *reinterpret_cast<const float4*>(W_ + (long)(n0 + row) * ldw_ + k0 + c4)\
                : make_float4(0.f, 0.f, 0.f, 0.f);                                       \
        }                                                                                \
    };                                                                                   \
    auto store_chunk = [&](int s) {                                                      \
        char* st = smem + s * G::STAGE;                                                  \
        _Pragma("unroll")                                                                \
        for (int q = 0; q < G::AV; q++) {                                                \
            int idx = tid + q * G::T;                                                    \
            int row = idx >> 3, c4 = (idx & 7) * 4;                                      \
            float4 h, l;                                                                 \
            tsplit(ra[q].x, h.x, l.x); tsplit(ra[q].y, h.y, l.y);                        \
            tsplit(ra[q].z, h.z, l.z); tsplit(ra[q].w, h.w, l.w);                        \
            *reinterpret_cast<float4*>(st + row * G::P32 + c4 * 4) = h;                  \
            store_lo(st + G::OFF_A16L, row, c4, l);                                      \
        }                                                                                \
        _Pragma("unroll")                                                                \
        for (int q = 0; q < G::BV; q++) {                                                \
            int idx = tid + q * G::T;                                                    \
            int row = idx >> 3, c4 = (idx & 7) * 4;                                      \
            float4 h, l;                                                                 \
            tsplit(rb[q].x, h.x, l.x); tsplit(rb[q].y, h.y, l.y);                        \
            tsplit(rb[q].z, h.z, l.z); tsplit(rb[q].w, h.w, l.w);                        \
            *reinterpret_cast<float4*>(st + G::OFF_B32 + row * G::P32 + c4 * 4) = h;     \
            store_lo(st + G::OFF_B16L, row, c4, l);                                      \
        }                                                                                \
    };                                                                                   \
    auto compute = [&](int s) {                                                          \
        const uint32_t base = dsm + s * G::STAGE;                                        \
        const uint32_t aHp = base + (uint32_t)((wm + (lane & 15)) * G::P32)              \
                           + (lane >> 4) * 16;                                           \
        const uint32_t bHp = base + G::OFF_B32                                           \
                           + (uint32_t)((wn + ((lane >> 3) & 1) * 8 + (lane & 7)) * G::P32)\
                           + (lane >> 4) * 16;                                           \
        const uint32_t aLp = base + G::OFF_A16L                                          \
                           + (uint32_t)((wm + (lane & 15)) * G::P16) + (lane >> 4) * 16; \
        const uint32_t bLp = base + G::OFF_B16L                                          \
                           + (uint32_t)((wn + (lane & 7)) * G::P16)                      \
                           + ((lane >> 3) & 1) * 16;                                     \
        _Pragma("unroll")                                                                \
        for (int t = 0; t < 2; t++) {                                                    \
            uint32_t a16[2][4], b16[G::NI][2];                                           \
            _Pragma("unroll")                                                            \
            for (int half = 0; half < 2; half++) {                                       \
                const int ks = 2 * t + half;                                             \
                uint32_t ah[2][4];                                                       \
                uint32_t bh[G::NI][2];                                                   \
                _Pragma("unroll")                                                        \
                for (int mi = 0; mi < 2; mi++)                                           \
                    ldsm_x4(ah[mi], aHp + mi * 16 * G::P32 + ks * 32);                   \
                _Pragma("unroll")                                                        \
                for (int p = 0; p < G::NI / 2; p++) {                                    \
                    uint32_t tt[4];                                                      \
                    ldsm_x4(tt, bHp + p * 16 * G::P32 + ks * 32);                        \
                    bh[2*p][0] = tt[0]; bh[2*p][1] = tt[2];                              \
                    bh[2*p+1][0] = tt[1]; bh[2*p+1][1] = tt[3];                          \
                }                                                                        \
                _Pragma("unroll")                                                        \
                for (int mi = 0; mi < 2; mi++)                                           \
                    _Pragma("unroll")                                                    \
                    for (int ni = 0; ni < G::NI; ni++)                                   \
                        mma1688(Chh[mi][ni], ah[mi], bh[ni][0], bh[ni][1]);              \
                _Pragma("unroll")                                                        \
                for (int mi = 0; mi < 2; mi++) {                                         \
                    a16[mi][2*half + 0] = pack2f(ah[mi][0], ah[mi][2]);                  \
                    a16[mi][2*half + 1] = pack2f(ah[mi][1], ah[mi][3]);                  \
                }                                                                        \
                _Pragma("unroll")                                                        \
                for (int ni = 0; ni < G::NI; ni++)                                       \
                    b16[ni][half] = pack2f(bh[ni][0], bh[ni][1]);                        \
            }                                                                            \
            uint32_t al[2][4], bl[G::NI][2];                                             \
            _Pragma("unroll")                                                            \
            for (int mi = 0; mi < 2; mi++)                                               \
                ldsm_x4(al[mi], aLp + mi * 16 * G::P16 + t * 32);                        \
            _Pragma("unroll")                                                            \
            for (int ni = 0; ni < G::NI; ni++)                                           \
                ldsm_x2(bl[ni], bLp + ni * 8 * G::P16 + t * 32);                         \
            _Pragma("unroll")                                                            \
            for (int mi = 0; mi < 2; mi++)                                               \
                _Pragma("unroll")                                                        \
                for (int ni = 0; ni < G::NI; ni++)                                       \
                    mma16816(Ccr[mi][ni], a16[mi], bl[ni]);                              \
            _Pragma("unroll")                                                            \
            for (int mi = 0; mi < 2; mi++)                                               \
                _Pragma("unroll")                                                        \
                for (int ni = 0; ni < G::NI; ni++)                                       \
                    mma16816(Ccr[mi][ni], al[mi], b16[ni]);                              \
        }                                                                                \
    };                                                                                   \
    const int nch = (K_ + G::BK - 1) / G::BK;                                            \
    load_chunk(0);                                                                       \
    store_chunk(0);                                                                      \
    __syncthreads();                                                                     \
    for (int i = 0; i < nch; i++) {                                                      \
        const int s = i & 1;                                                             \
        if (i + 1 < nch) load_chunk(i + 1);                                              \
        compute(s);                                                                      \
        if (i + 1 < nch) {                                                               \
            store_chunk(s ^ 1);                                                          \
            __syncthreads();                                                             \
        }                                                                                \
    }

// ------------------------- generic GEMM -------------------------
template<int BN>
__global__ void __launch_bounds__(256, 2)
gemm_mma(const float* __restrict__ A, int lda,
         const float* __restrict__ W, int ldw,
         float* __restrict__ C, int ldc, int K,
         const float* __restrict__ bias,
         const float* __restrict__ bias2,
         int relu)
{
    using G = GC<BN>;
    extern __shared__ char smem[];
    const uint32_t dsm = smem_u32(smem);
    GEMM_BODY(G, A, lda, W, ldw, K)

    const float sc = 1.0f / 2048.0f;
#pragma unroll
    for (int mi = 0; mi < 2; mi++)
#pragma unroll
        for (int ni = 0; ni < G::NI; ni++)
#pragma unroll
            for (int h = 0; h < 2; h++) {
                long row = m0 + wm + mi * 16 + (lane >> 2) + h * 8;
                int  col = n0 + wn + ni * 8 + (lane & 3) * 2;
                float v0 = Chh[mi][ni][2 * h + 0] + sc * Ccr[mi][ni][2 * h + 0];
                float v1 = Chh[mi][ni][2 * h + 1] + sc * Ccr[mi][ni][2 * h + 1];
                if (bias)  { v0 += bias[col];  v1 += bias[col + 1]; }
                if (bias2) { v0 += bias2[col]; v1 += bias2[col + 1]; }
                if (relu)  { v0 = fmaxf(v0, 0.f); v1 = fmaxf(v1, 0.f); }
                *reinterpret_cast<float2*>(C + row * (long)ldc + col) = make_float2(v0, v1);
            }
}

// ------------------------- fused recurrent GEMM + LSTM pointwise -------------
__global__ void __launch_bounds__(256, 2)
gemm_lstm(const float* __restrict__ Hin,
          const float* __restrict__ Whh,
          const float* __restrict__ addend,   // XS + t*G4H, ld = TT*G4H
          float* __restrict__ Hout,
          float* __restrict__ Cs)
{
    constexpr int BN = 128;
    using G = GC<128>;
    extern __shared__ char smem[];
    const uint32_t dsm = smem_u32(smem);
    GEMM_BODY(G, Hin, HH, Whh, HH, HH)

    // fused epilogue: gates -> smem -> LSTM pointwise
    __syncthreads();
    constexpr int GP = 132;
    float* gt = reinterpret_cast<float*>(smem);
    const float sc = 1.0f / 2048.0f;
#pragma unroll
    for (int mi = 0; mi < 2; mi++)
#pragma unroll
        for (int ni = 0; ni < G::NI; ni++)
#pragma unroll
            for (int h = 0; h < 2; h++) {
                int rl = wm + mi * 16 + (lane >> 2) + h * 8;
                int cl = wn + ni * 8 + (lane & 3) * 2;
                long row = m0 + rl;
                int  col = n0 + cl;
                float2 ad = *reinterpret_cast<const float2*>(
                    addend + row * (long)(TT * G4H) + col);
                gt[rl * GP + cl]     = Chh[mi][ni][2*h+0] + sc * Ccr[mi][ni][2*h+0] + ad.x;
                gt[rl * GP + cl + 1] = Chh[mi][ni][2*h+1] + sc * Ccr[mi][ni][2*h+1] + ad.y;
            }
    __syncthreads();

    const int u0 = n0 >> 2;
    for (int q = tid; q < 64 * 32; q += 256) {
        int r = q >> 5;
        int u = q & 31;
        float4 g4 = *reinterpret_cast<float4*>(gt + r * GP + u * 4);  // i,f,g,o
        size_t idx = (size_t)(m0 + r) * HH + (u0 + u);
        float cold = Cs[idx];
        float c = sigmoidf(g4.y) * cold + sigmoidf(g4.x) * tanhf(g4.z);
        Cs[idx] = c;
        Hout[idx] = sigmoidf(g4.w) * tanhf(c);
    }
}

// ------------------------- small kernels -------------------------
__global__ void zero_kernel(float* __restrict__ p, size_t n) {
    size_t i = (size_t)blockIdx.x * blockDim.x + threadIdx.x;
    if (i < n) p[i] = 0.f;
}

// permute LSTM weights to gate-interleaved layout: n -> 4*(n%512) + n/512
__global__ void perm_kernel(const float* __restrict__ Wih, const float* __restrict__ Whh,
                            const float* __restrict__ bih, const float* __restrict__ bhh,
                            float* __restrict__ Wih2, float* __restrict__ Whh2,
                            float* __restrict__ bsum2) {
    int n = blockIdx.x;
    int np = 4 * (n & 511) + (n >> 9);
    for (int i = threadIdx.x; i < DD; i += blockDim.x)
        Wih2[(size_t)np * DD + i] = Wih[(size_t)n * DD + i];
    for (int i = threadIdx.x; i < HH; i += blockDim.x)
        Whh2[(size_t)np * HH + i] = Whh[(size_t)n * HH + i];
    if (threadIdx.x == 0) bsum2[np] = bih[n] + bhh[n];
}

// t=0 LSTM pointwise on interleaved XS (h0 = c0 = 0)
__global__ void lstm0_il(const float* __restrict__ XS0, float* __restrict__ Hs,
                         float* __restrict__ Cs) {
    int idx = blockIdx.x * blockDim.x + threadIdx.x;
    if (idx >= BATCH * HH) return;
    int b = idx / HH, j = idx % HH;
    float4 g4 = *reinterpret_cast<const float4*>(XS0 + (size_t)b * (TT * G4H) + 4 * j);
    float c = sigmoidf(g4.x) * tanhf(g4.z);
    Cs[idx] = c;
    Hs[idx] = sigmoidf(g4.w) * tanhf(c);
}

__global__ void flow2_kernel(const float* __restrict__ FHp,
                             const float* __restrict__ fw2,
                             const float* __restrict__ fb2,
                             float* __restrict__ FLOWp,
                             float* __restrict__ out) {
    __shared__ float w[NF * HH];
    int tid = threadIdx.x;
    for (int q = tid; q < NF * HH; q += blockDim.x) w[q] = fw2[q];
    __syncthreads();
    int warp = tid >> 5, lane = tid & 31;
    int b = blockIdx.x * 8 + warp;
    const float* r = FHp + (size_t)b * HH;
    float a0 = 0.f, a1 = 0.f, a2 = 0.f, a3 = 0.f;
    for (int k = lane; k < HH; k += 32) {
        float v = r[k];
        a0 += v * w[k];
        a1 += v * w[HH + k];
        a2 += v * w[2 * HH + k];
        a3 += v * w[3 * HH + k];
    }
#pragma unroll
    for (int off = 16; off; off >>= 1) {
        a0 += __shfl_xor_sync(0xffffffffu, a0, off);
        a1 += __shfl_xor_sync(0xffffffffu, a1, off);
        a2 += __shfl_xor_sync(0xffffffffu, a2, off);
        a3 += __shfl_xor_sync(0xffffffffu, a3, off);
    }
    if (lane == 0) {
        a0 += fb2[0]; a1 += fb2[1]; a2 += fb2[2]; a3 += fb2[3];
        float m = fmaxf(fmaxf(a0, a1), fmaxf(a2, a3));
        float e0 = expf(a0 - m), e1 = expf(a1 - m), e2 = expf(a2 - m), e3 = expf(a3 - m);
        float inv = 1.f / (e0 + e1 + e2 + e3);
        float p0 = e0 * inv, p1 = e1 * inv, p2 = e2 * inv, p3 = e3 * inv;
        FLOWp[b * 4 + 0] = p0; FLOWp[b * 4 + 1] = p1;
        FLOWp[b * 4 + 2] = p2; FLOWp[b * 4 + 3] = p3;
        out[OFF_FLOW + b * 4 + 0] = p0; out[OFF_FLOW + b * 4 + 1] = p1;
        out[OFF_FLOW + b * 4 + 2] = p2; out[OFF_FLOW + b * 4 + 3] = p3;
    }
}

__global__ void build_comb(const float* __restrict__ x,
                           const float* __restrict__ Hs,
                           const float* __restrict__ FLOWp,
                           float* __restrict__ comb) {
    size_t idx = (size_t)blockIdx.x * blockDim.x + threadIdx.x;
    if (idx >= (size_t)BATCH * KCOMB) return;
    int b = (int)(idx / KCOMB), c = (int)(idx % KCOMB);
    float v;
    if (c < DD)            v = x[(size_t)b * DD + c];
    else if (c < DD + HH)  v = Hs[(size_t)b * HH + (c - DD)];
    else                   v = FLOWp[b * 4 + (c - DD - HH)];
    comb[idx] = v;
}

__global__ void final_gate_kernel(const float* __restrict__ adjraw,
                                  const float* __restrict__ flow,
                                  const float* __restrict__ spec,
                                  float* __restrict__ out) {
    __shared__ float s_spec[EE * NF];
    __shared__ float s_usage[EE];
    int tid = threadIdx.x;
    if (tid < EE * NF) s_spec[tid] = spec[tid];
    if (tid < EE)      s_usage[tid] = 0.f;
    __syncthreads();

    int warp = tid >> 5, lane = tid & 31;
    int b = blockIdx.x * 8 + warp;

    float f0 = flow[b * 4 + 0], f1 = flow[b * 4 + 1], f2 = flow[b * 4 + 2], f3 = flow[b * 4 + 3];
    int e0 = lane, e1 = lane + 32;
    float sp0 = 0.1f * (f0 * s_spec[e0 * 4 + 0] + f1 * s_spec[e0 * 4 + 1] +
                        f2 * s_spec[e0 * 4 + 2] + f3 * s_spec[e0 * 4 + 3]);
    float sp1 = 0.1f * (f0 * s_spec[e1 * 4 + 0] + f1 * s_spec[e1 * 4 + 1] +
                        f2 * s_spec[e1 * 4 + 2] + f3 * s_spec[e1 * 4 + 3]);
    float l0 = adjraw[(size_t)b * EE + e0] + sp0;
    float l1 = adjraw[(size_t)b * EE + e1] + sp1;
    out[OFF_ADJ + (size_t)b * EE + e0] = l0;
    out[OFF_ADJ + (size_t)b * EE + e1] = l1;

    float m = fmaxf(l0, l1);
#pragma unroll
    for (int off = 16; off; off >>= 1) m = fmaxf(m, __shfl_xor_sync(0xffffffffu, m, off));
    float x0 = expf(l0 - m), x1 = expf(l1 - m);
    float s = x0 + x1;
#pragma unroll
    for (int off = 16; off; off >>= 1) s += __shfl_xor_sync(0xffffffffu, s, off);
    float inv_s = 1.f / s;
    float p0 = x0 * inv_s, p1 = x1 * inv_s;

    atomicAdd(&s_usage[e0], p0);
    atomicAdd(&s_usage[e1], p1);

    float tp[8]; int ti[8];
    float v0 = p0, v1 = p1;
#pragma unroll
    for (int it = 0; it < 8; it++) {
        float v; int bi;
        if (v1 > v0) { v = v1; bi = e1; } else { v = v0; bi = e0; }
#pragma unroll
        for (int off = 16; off; off >>= 1) {
            float ov = __shfl_xor_sync(0xffffffffu, v, off);
            int   oi = __shfl_xor_sync(0xffffffffu, bi, off);
            if (ov > v || (ov == v && oi < bi)) { v = ov; bi = oi; }
        }
        tp[it] = v; ti[it] = bi;
        if (bi == e0) v0 = -1.f;
        if (bi == e1) v1 = -1.f;
    }
    float ssum = 0.f;
#pragma unroll
    for (int it = 0; it < 8; it++) ssum += tp[it];
    float invn = 1.f / (ssum + 1e-8f);
    if (lane < 8) {
        out[OFF_TOPP + (size_t)b * 8 + lane] = tp[lane] * invn;
        out[OFF_TOPI + (size_t)b * 8 + lane] = (float)ti[lane];
    }
    __syncthreads();
    if (tid < EE) atomicAdd(&out[OFF_USAGE + tid], s_usage[tid]);
}

__global__ void loss_kernel(float* __restrict__ out) {
    __shared__ float red[EE];
    int t = threadIdx.x;
    float u = out[OFF_USAGE + t] / (float)BATCH;
    out[OFF_USAGE + t] = u;
    red[t] = -(1.0f / 64.f) * log1pf(64.f * u - 1.f);
    __syncthreads();
    for (int s = 32; s; s >>= 1) {
        if (t < s) red[t] += red[t + s];
        __syncthreads();
    }
    if (t == 0) out[OFF_LOSS] = red[0] / 64.f;
}

// ------------------------- launch -------------------------
extern "C" void kernel_launch(void* const* d_in, const int* in_sizes, int n_in,
                              void* d_out, int out_size) {
    const float* x        = (const float*)d_in[0];
    const float* context  = (const float*)d_in[1];
    const float* W_ih     = (const float*)d_in[2];
    const float* W_hh     = (const float*)d_in[3];
    const float* b_ih     = (const float*)d_in[4];
    const float* b_hh     = (const float*)d_in[5];
    const float* fw1      = (const float*)d_in[6];
    const float* fb1      = (const float*)d_in[7];
    const float* fw2      = (const float*)d_in[8];
    const float* fb2      = (const float*)d_in[9];
    const float* gw1      = (const float*)d_in[10];
    const float* gb1      = (const float*)d_in[11];
    const float* gw2      = (const float*)d_in[12];
    const float* gb2      = (const float*)d_in[13];
    const float* espec    = (const float*)d_in[14];
    float* out = (float*)d_out;

    float *XS, *Ha, *Hb, *Cs, *FH, *FLOW, *COMB, *G1, *ADJ, *WIH2, *WHH2, *BSUM2;
    cudaGetSymbolAddress((void**)&XS,    d_XS);
    cudaGetSymbolAddress((void**)&Ha,    d_Hst);
    cudaGetSymbolAddress((void**)&Hb,    d_Hst2);
    cudaGetSymbolAddress((void**)&Cs,    d_Cst);
    cudaGetSymbolAddress((void**)&FH,    d_FH);
    cudaGetSymbolAddress((void**)&FLOW,  d_FLOW);
    cudaGetSymbolAddress((void**)&COMB,  d_COMB);
    cudaGetSymbolAddress((void**)&G1,    d_G1);
    cudaGetSymbolAddress((void**)&ADJ,   d_ADJ);
    cudaGetSymbolAddress((void**)&WIH2,  d_WIH2);
    cudaGetSymbolAddress((void**)&WHH2,  d_WHH2);
    cudaGetSymbolAddress((void**)&BSUM2, d_BSUM2);

    const int SMEM128 = 2 * GC<128>::STAGE;   // 86016
    const int SMEM64  = 2 * GC<64>::STAGE;    // 57344
    cudaFuncSetAttribute((void*)gemm_mma<128>,
                         cudaFuncAttributeMaxDynamicSharedMemorySize, SMEM128);
    cudaFuncSetAttribute((void*)gemm_mma<64>,
                         cudaFuncAttributeMaxDynamicSharedMemorySize, SMEM64);
    cudaFuncSetAttribute((void*)gemm_lstm,
                         cudaFuncAttributeMaxDynamicSharedMemorySize, SMEM128);

    // 1: permute LSTM weights + bias to gate-interleaved layout
    perm_kernel<<<G4H, 256>>>(W_ih, W_hh, b_ih, b_hh, WIH2, WHH2, BSUM2);

    // 2: flow hidden: relu(x @ fw1^T + fb1)
    gemm_mma<128><<<dim3(HH / 128, BATCH / 64), 256, SMEM128>>>(
        x, DD, fw1, DD, FH, HH, DD, fb1, nullptr, 1);

    // 3: flow_state softmax head
    flow2_kernel<<<BATCH / 8, 256>>>(FH, fw2, fb2, FLOW, out);

    // 4: XS = context @ WIH2^T + BSUM2 (interleaved cols)  <-- profiled slot
    gemm_mma<128><<<dim3(G4H / 128, (BATCH * TT) / 64), 256, SMEM128>>>(
        context, DD, WIH2, DD, XS, G4H, DD, BSUM2, nullptr, 0);

    // 5: t = 0 pointwise (h0 = c0 = 0), interleaved XS
    lstm0_il<<<(BATCH * HH + 255) / 256, 256>>>(XS, Ha, Cs);

    // 6..12: fused recurrent GEMM + LSTM pointwise, double-buffered H
    float* Hin = Ha;
    float* Hout = Hb;
    for (int t = 1; t < TT; t++) {
        gemm_lstm<<<dim3(G4H / 128, BATCH / 64), 256, SMEM128>>>(
            Hin, WHH2, XS + (size_t)t * G4H, Hout, Cs);
        float* tmp = Hin; Hin = Hout; Hout = tmp;
    }

    build_comb<<<(unsigned)(((size_t)BATCH * KCOMB + 255) / 256), 256>>>(x, Hin, FLOW, COMB);

    // gate hidden: relu(combined @ gw1^T + gb1), K = 1540 (ragged last chunk)
    gemm_mma<128><<<dim3(DD / 128, BATCH / 64), 256, SMEM128>>>(
        COMB, KCOMB, gw1, KCOMB, G1, DD, KCOMB, gb1, nullptr, 1);

    // gate logits: G1 @ gw2^T + gb2
    gemm_mma<64><<<dim3(EE / 64, BATCH / 64), 256, SMEM64>>>(
        G1, DD, gw2, DD, ADJ, EE, DD, gb2, nullptr, 0);

    zero_kernel<<<1, 64>>>(out + OFF_USAGE, EE);
    final_gate_kernel<<<BATCH / 8, 256>>>(ADJ, FLOW, espec, out);
    loss_kernel<<<1, 64>>>(out);
}